// round 2
// baseline (speedup 1.0000x reference)
#include <cuda_runtime.h>
#include <cstddef>

#define BB 64
#define SS 2048
#define II 64
#define HH 128

// 64 MB scratch for wx = X @ W (reused by both layers)
__device__ float g_wx[BB * SS * HH];

// ---------------- packed f32x2 helpers ----------------
__device__ __forceinline__ unsigned long long ffma2(unsigned long long a,
                                                    unsigned long long b,
                                                    unsigned long long c) {
    unsigned long long d;
    asm("fma.rn.f32x2 %0, %1, %2, %3;" : "=l"(d) : "l"(a), "l"(b), "l"(c));
    return d;
}
__device__ __forceinline__ unsigned long long fadd2(unsigned long long a,
                                                    unsigned long long b) {
    unsigned long long d;
    asm("add.rn.f32x2 %0, %1, %2;" : "=l"(d) : "l"(a), "l"(b));
    return d;
}
__device__ __forceinline__ void unpack2(unsigned long long s, float& lo, float& hi) {
    asm("mov.b64 {%0, %1}, %2;" : "=f"(lo), "=f"(hi) : "l"(s));
}
__device__ __forceinline__ unsigned long long pack2(float lo, float hi) {
    unsigned long long r;
    asm("mov.b64 %0, {%1, %2};" : "=l"(r) : "f"(lo), "f"(hi));
    return r;
}

__device__ __forceinline__ float sigmf(float x) {
    return __fdividef(1.0f, 1.0f + __expf(-x));
}
__device__ __forceinline__ float tanh_ap(float x) {
    float y;
    asm("tanh.approx.f32 %0, %1;" : "=f"(y) : "f"(x));
    return y;
}

// ---------------- GEMM: Y[M,128] = X[M,K] @ W[K,128] -> g_wx ----------------
// 256 threads: j = tid&127 (output column), rowpar = tid>>7 (row parity).
// W column j packed by k-pairs into registers ({W[2i][j], W[2i+1][j]}).
// X rows staged plain in SMEM; inner loop = LDS.128 broadcast + 2x FFMA2.
// No shuffles: the f32x2 lo/hi lanes hold even-k/odd-k partial sums, one add at end.
template <int K>
__global__ void __launch_bounds__(256, 1)
gemm_wx_kernel(const float* __restrict__ X, const float* __restrict__ W,
               int rows_per_cta) {
    constexpr int CHUNK = 32;
    __shared__ __align__(16) float xs[CHUNK * K];

    const int tid = threadIdx.x;
    const int j = tid & 127;
    const int rowpar = tid >> 7;

    unsigned long long wreg[K / 2];
#pragma unroll
    for (int i = 0; i < K / 2; i++) {
        wreg[i] = pack2(W[(size_t)(2 * i) * HH + j], W[(size_t)(2 * i + 1) * HH + j]);
    }

    const int row0 = blockIdx.x * rows_per_cta;

    for (int rc = 0; rc < rows_per_cta; rc += CHUNK) {
        __syncthreads();  // previous chunk fully consumed
        const float4* src = reinterpret_cast<const float4*>(X + (size_t)(row0 + rc) * K);
        float4* dst = reinterpret_cast<float4*>(xs);
        for (int i = tid; i < CHUNK * K / 4; i += 256) dst[i] = src[i];
        __syncthreads();

        for (int r = rowpar; r < CHUNK; r += 2) {
            const ulonglong2* xp = reinterpret_cast<const ulonglong2*>(xs + r * K);
            unsigned long long a0 = 0, a1 = 0, a2 = 0, a3 = 0;
#pragma unroll
            for (int i = 0; i < K / 4; i++) {
                ulonglong2 v = xp[i];
                if (i & 1) {
                    a2 = ffma2(v.x, wreg[2 * i], a2);
                    a3 = ffma2(v.y, wreg[2 * i + 1], a3);
                } else {
                    a0 = ffma2(v.x, wreg[2 * i], a0);
                    a1 = ffma2(v.y, wreg[2 * i + 1], a1);
                }
            }
            unsigned long long s = fadd2(fadd2(a0, a2), fadd2(a1, a3));
            float lo, hi;
            unpack2(s, lo, hi);
            g_wx[(size_t)(row0 + rc + r) * HH + j] = lo + hi;
        }
    }
}

// ---------------- Recurrent scan: one batch row per CTA, 256 threads ----------------
// Lane pair (2j, 2j+1) owns column j; half = tid&1 owns k-range [half*64, half*64+64).
// u column packed by k-pairs in registers; h plain in SMEM ping-pong (broadcast reads).
// Reduce: local lo+hi, then ONE shfl.bfly(1). Both halves compute the identical h
// update (bitwise same); only half==0 writes h/out.
__global__ void __launch_bounds__(256, 1)
scan_kernel(const float* __restrict__ u, const float* __restrict__ bg,
            const float* __restrict__ bu, const float* __restrict__ zeta,
            const float* __restrict__ nu, const float* __restrict__ lambd,
            const float* __restrict__ gamma, float* __restrict__ out,
            float* __restrict__ hT) {
    const int b = blockIdx.x;
    const int tid = threadIdx.x;
    const int j = tid >> 1;
    const int half = tid & 1;
    const int kbase = half * 64;

    __shared__ __align__(16) float hbuf[2][128];

    unsigned long long ureg[32];
#pragma unroll
    for (int i = 0; i < 32; i++) {
        ureg[i] = pack2(u[(size_t)(kbase + 2 * i) * HH + j],
                        u[(size_t)(kbase + 2 * i + 1) * HH + j]);
    }

    const float bgj = bg[j];
    const float buj = bu[j];
    const float sz = sigmf(zeta[0]);
    const float sn = sigmf(nu[0]);
    const float gc = fminf(fmaxf(gamma[0], 0.0f), 1.0f);
    const float omgl = (1.0f - gc) * lambd[0];

    if (!half) hbuf[0][j] = 0.0f;
    float h_old = 0.0f;

    const float* wxb = g_wx + (size_t)b * SS * HH + j;
    float* outb = out + (size_t)b * SS * HH + j;

    float ring[4];
#pragma unroll
    for (int i = 0; i < 4; i++) ring[i] = __ldg(wxb + (size_t)i * HH);

    __syncthreads();

    int buf = 0;
#pragma unroll 4
    for (int s = 0; s < SS; s++) {
        float wxv = ring[s & 3];
        if (s + 4 < SS) ring[s & 3] = __ldg(wxb + (size_t)(s + 4) * HH);

        const ulonglong2* hp = reinterpret_cast<const ulonglong2*>(&hbuf[buf][kbase]);
        unsigned long long a0 = 0, a1 = 0, a2 = 0, a3 = 0;
#pragma unroll
        for (int i = 0; i < 16; i++) {
            ulonglong2 v = hp[i];
            if (i & 1) {
                a2 = ffma2(v.x, ureg[2 * i], a2);
                a3 = ffma2(v.y, ureg[2 * i + 1], a3);
            } else {
                a0 = ffma2(v.x, ureg[2 * i], a0);
                a1 = ffma2(v.y, ureg[2 * i + 1], a1);
            }
        }
        unsigned long long ssum = fadd2(fadd2(a0, a2), fadd2(a1, a3));
        float lo, hi;
        unpack2(ssum, lo, hi);
        float sloc = lo + hi;
        float so = __shfl_xor_sync(0xffffffffu, sloc, 1);
        float pre = (sloc + so) + wxv;

        float z = sigmf(pre + bgj);
        float hh = tanh_ap(pre + buj);
        float hnew = z * h_old + (sz * (1.0f - z) + sn) * hh;
        float hc = fmaf(gc, hnew, omgl);
        h_old = hc;

        if (!half) {
            outb[(size_t)s * HH] = hc;
            hbuf[buf ^ 1][j] = hc;
        }
        __syncthreads();
        buf ^= 1;
    }

    if (!half) hT[b * HH + j] = h_old;
}

// ---------------- launch ----------------
extern "C" void kernel_launch(void* const* d_in, const int* in_sizes, int n_in,
                              void* d_out, int out_size) {
    const float* x      = (const float*)d_in[0];
    const float* w0     = (const float*)d_in[1];
    const float* u0     = (const float*)d_in[2];
    const float* bg0    = (const float*)d_in[3];
    const float* bu0    = (const float*)d_in[4];
    const float* zeta0  = (const float*)d_in[5];
    const float* nu0    = (const float*)d_in[6];
    const float* lambd0 = (const float*)d_in[7];
    const float* gamma0 = (const float*)d_in[8];
    const float* w1     = (const float*)d_in[9];
    const float* u1     = (const float*)d_in[10];
    const float* bg1    = (const float*)d_in[11];
    const float* bu1    = (const float*)d_in[12];
    const float* zeta1  = (const float*)d_in[13];
    const float* nu1    = (const float*)d_in[14];
    const float* lambd1 = (const float*)d_in[15];
    const float* gamma1 = (const float*)d_in[16];

    float* out = (float*)d_out;                  // out1 region [B*S*H]
    float* h0T = out + (size_t)BB * SS * HH;     // h_n[0]
    float* h1T = h0T + (size_t)BB * HH;          // h_n[1]

    const int M = BB * SS;       // 131072 rows
    const int GRID = 1024;
    const int RPC = M / GRID;    // 128 rows per CTA

    // Layer 0: wx0 = x @ w0 -> g_wx ; scan0 -> out (as out0 scratch) + h0T
    gemm_wx_kernel<II><<<GRID, 256>>>(x, w0, RPC);
    scan_kernel<<<BB, 256>>>(u0, bg0, bu0, zeta0, nu0, lambd0, gamma0, out, h0T);

    // Layer 1: wx1 = out0 @ w1 -> g_wx ; scan1 -> out (final) + h1T
    gemm_wx_kernel<HH><<<GRID, 256>>>(out, w1, RPC);
    scan_kernel<<<BB, 256>>>(u1, bg1, bu1, zeta1, nu1, lambd1, gamma1, out, h1T);
}